// round 12
// baseline (speedup 1.0000x reference)
#include <cuda_runtime.h>
#include <cuda_fp16.h>
#include <cstdint>

#define E_N 100000
#define R_N 64
#define I_N 256
#define O_N 256
#define TILE_M 128
#define N_TILES ((E_N + TILE_M - 1) / TILE_M)   // 782

// smem: A double buffer only. s_w (init-only, 64KB) overlaps it.
#define A_BUF    18432                 // one hi or lo plane, 128 rows x 144B
#define SM_A0    0                     // buf0: hi @0, lo @18432
#define SM_A1    36864                 // buf1: hi, lo
#define SM_TOT   73728
#define A_STRIDE 144                   // %128==16 -> conflict-free LDSM

__device__ float g_wpart[16 * R_N * O_N];
__device__ float g_wsum[R_N * O_N];

// ---------------------------------------------------------------------------
// Kernel 1: W partial sums (1024 blocks = (r, i-16th)), then tiny final pass.
// ---------------------------------------------------------------------------
__global__ __launch_bounds__(256, 8)
void wsum_part_kernel(const float* __restrict__ W) {
    const int r = blockIdx.x & 63;
    const int part = blockIdx.x >> 6;
    const int o = threadIdx.x;
    const float* base = W + ((size_t)(r * I_N + part * 16)) * O_N + o;
    float s = 0.f;
#pragma unroll
    for (int i = 0; i < 16; ++i) s += base[(size_t)i * O_N];
    g_wpart[(part * R_N + r) * O_N + o] = s;
}

__global__ void wsum_final_kernel() {
    const int r = blockIdx.x, o = threadIdx.x;
    float s = 0.f;
#pragma unroll
    for (int p = 0; p < 16; ++p) s += g_wpart[(p * R_N + r) * O_N + o];
    g_wsum[r * O_N + o] = s;
}

// ---------------------------------------------------------------------------
// helpers
// ---------------------------------------------------------------------------
static __device__ __forceinline__ void mma16816(float* acc, const uint32_t* a,
                                                uint32_t b0, uint32_t b1) {
    asm volatile(
        "mma.sync.aligned.m16n8k16.row.col.f32.f16.f16.f32 "
        "{%0,%1,%2,%3}, {%4,%5,%6,%7}, {%8,%9}, {%0,%1,%2,%3};"
        : "+f"(acc[0]), "+f"(acc[1]), "+f"(acc[2]), "+f"(acc[3])
        : "r"(a[0]), "r"(a[1]), "r"(a[2]), "r"(a[3]), "r"(b0), "r"(b1));
}
static __device__ __forceinline__ void ldsm4(uint32_t* r, uint32_t saddr) {
    asm volatile("ldmatrix.sync.aligned.m8n8.x4.shared.b16 {%0,%1,%2,%3}, [%4];"
                 : "=r"(r[0]), "=r"(r[1]), "=r"(r[2]), "=r"(r[3]) : "r"(saddr));
}
static __device__ __forceinline__ uint32_t pack2(__half a, __half b) {
    __half2 h; h.x = a; h.y = b;
    return *(uint32_t*)&h;
}
static __device__ __forceinline__ void split16(float v, __half& hi, __half& lo) {
    hi = __float2half_rn(v);
    lo = __float2half_rn(v - __half2float(hi));
}
// FMA-pipe reciprocal (no MUFU): magic seed + 2 Newton iterations
static __device__ __forceinline__ float frcp(float y) {
    float r = __uint_as_float(0x7EF311C3u - __float_as_uint(y));
    r = r * __fmaf_rn(-y, r, 2.0f);
    r = r * __fmaf_rn(-y, r, 2.0f);
    return r;
}

// ---------------------------------------------------------------------------
// Kernel 2: single-wave persistent main kernel, 2 CTAs/SM, 8 warps.
// Per tile: prep (x row-sum + cs recip + fp16 hi/lo split -> A[buf]) ->
// one barrier -> HMMA + store. A double-buffered => 1 barrier/tile.
// ---------------------------------------------------------------------------
__global__ __launch_bounds__(256, 2)
void rgcn_hmma_kernel(const float* __restrict__ x,
                      const float* __restrict__ cs,
                      float* __restrict__ out) {
    extern __shared__ __align__(16) char sm[];
    const uint32_t sbase = (uint32_t)__cvta_generic_to_shared(sm);
    const int t = threadIdx.x;
    const int warp = t >> 5, lane = t & 31;

    // ---- init: stage Wsum in smem (overlaps A bufs), extract B frags ------
    float* s_w = (float*)sm;
#pragma unroll 4
    for (int i = 0; i < 64; ++i) {
        int idx = i * 256 + t;
        s_w[idx] = g_wsum[idx];
    }
    __syncthreads();

    uint32_t bh[4][4][2], bl[4][4][2];
    {
        const int n = warp * 32 + (lane >> 2);
#pragma unroll
        for (int nt = 0; nt < 4; ++nt)
#pragma unroll
            for (int ks = 0; ks < 4; ++ks) {
                int kb = ks * 16 + 2 * (lane & 3);
                int nn = n + nt * 8;
                float w00 = s_w[kb * 256 + nn];
                float w01 = s_w[(kb + 1) * 256 + nn];
                float w10 = s_w[(kb + 8) * 256 + nn];
                float w11 = s_w[(kb + 9) * 256 + nn];
                __half h00, l00, h01, l01, h10, l10, h11, l11;
                split16(w00, h00, l00); split16(w01, h01, l01);
                split16(w10, h10, l10); split16(w11, h11, l11);
                bh[nt][ks][0] = pack2(h00, h01); bh[nt][ks][1] = pack2(h10, h11);
                bl[nt][ks][0] = pack2(l00, l01); bl[nt][ks][1] = pack2(l10, l11);
            }
    }
    __syncthreads();   // s_w dead; A buffers usable

    const int grid = gridDim.x;
    const int el = t >> 1, kh = t & 1;   // prep mapping: entity, k/x half
    const float4* __restrict__ x4 = (const float4*)x;
    const float4* __restrict__ cs4 = (const float4*)cs;

    int cnt = 0;
    for (int ti = blockIdx.x; ti < N_TILES; ti += grid, ++cnt) {
        const int buf = cnt & 1;
        const int ebase = ti * TILE_M;

        // ================= PREP ============================================
        {
            int e = ebase + el;
            if (e > E_N - 1) e = E_N - 1;

            // x row-sum: this thread sums half the row (128 floats, 32 LDG.128)
            const float4* xp = x4 + (size_t)e * 64 + kh * 32;
            float a0 = 0.f, a1 = 0.f, a2 = 0.f, a3 = 0.f;
#pragma unroll
            for (int i = 0; i < 32; i += 4) {
                float4 v0 = xp[i], v1 = xp[i + 1], v2 = xp[i + 2], v3 = xp[i + 3];
                a0 += (v0.x + v0.y) + (v0.z + v0.w);
                a1 += (v1.x + v1.y) + (v1.z + v1.w);
                a2 += (v2.x + v2.y) + (v2.z + v2.w);
                a3 += (v3.x + v3.y) + (v3.z + v3.w);
            }
            float hs = (a0 + a1) + (a2 + a3);
            float xs = hs + __shfl_xor_sync(0xffffffffu, hs, 1);

            // a[e][k] = xs / cs[e][k] for this thread's 32 k values
            const float4* cp = cs4 + (size_t)e * 16 + kh * 8;
            uint32_t hw[16], lw[16];
#pragma unroll
            for (int q = 0; q < 8; ++q) {
                float4 c = cp[q];
                float v0 = xs * frcp(c.x);
                float v1 = xs * frcp(c.y);
                float v2 = xs * frcp(c.z);
                float v3 = xs * frcp(c.w);
                __half h0, l0, h1, l1, h2, l2, h3, l3;
                split16(v0, h0, l0); split16(v1, h1, l1);
                split16(v2, h2, l2); split16(v3, h3, l3);
                hw[2 * q] = pack2(h0, h1); hw[2 * q + 1] = pack2(h2, h3);
                lw[2 * q] = pack2(l0, l1); lw[2 * q + 1] = pack2(l2, l3);
            }
            uint32_t off = (buf ? SM_A1 : SM_A0) + el * A_STRIDE + kh * 64;
            uint4* dh = (uint4*)(sm + off);
            uint4* dl = (uint4*)(sm + off + A_BUF);
#pragma unroll
            for (int q = 0; q < 4; ++q) {
                dh[q] = make_uint4(hw[4 * q], hw[4 * q + 1], hw[4 * q + 2], hw[4 * q + 3]);
                dl[q] = make_uint4(lw[4 * q], lw[4 * q + 1], lw[4 * q + 2], lw[4 * q + 3]);
            }
        }
        __syncthreads();   // A[buf] ready (also orders: all MMA[cnt-1] done)

        // ================= MMA + STORE =====================================
        {
            const uint32_t ah_base = sbase + (buf ? SM_A1 : SM_A0);
            const uint32_t al_base = ah_base + A_BUF;
            const uint32_t lrow = (lane & 7) + ((lane >> 3) & 1) * 8;
            const uint32_t lcol = (lane >> 4) * 16;
            const int gr = lane >> 2;
            const int col = warp * 32 + (lane & 3) * 2;

#pragma unroll 1
            for (int m0 = 0; m0 < TILE_M; m0 += 16) {
                uint32_t fo = (m0 + lrow) * A_STRIDE + lcol;
                float acc[4][4];
#pragma unroll
                for (int nt = 0; nt < 4; ++nt)
                    acc[nt][0] = acc[nt][1] = acc[nt][2] = acc[nt][3] = 0.f;
#pragma unroll
                for (int ks = 0; ks < 4; ++ks) {
                    uint32_t ah[4], al[4];
                    ldsm4(ah, ah_base + fo + ks * 32);
                    ldsm4(al, al_base + fo + ks * 32);
#pragma unroll
                    for (int nt = 0; nt < 4; ++nt) {
                        mma16816(acc[nt], ah, bh[nt][ks][0], bh[nt][ks][1]);
                        mma16816(acc[nt], ah, bl[nt][ks][0], bl[nt][ks][1]);
                        mma16816(acc[nt], al, bh[nt][ks][0], bh[nt][ks][1]);
                    }
                }
                int e0 = ebase + m0 + gr, e1 = e0 + 8;
                if (e0 < E_N) {
                    float* p = out + (size_t)e0 * O_N + col;
#pragma unroll
                    for (int nt = 0; nt < 4; ++nt)
                        *(float2*)(p + nt * 8) = make_float2(acc[nt][0], acc[nt][1]);
                }
                if (e1 < E_N) {
                    float* p = out + (size_t)e1 * O_N + col;
#pragma unroll
                    for (int nt = 0; nt < 4; ++nt)
                        *(float2*)(p + nt * 8) = make_float2(acc[nt][2], acc[nt][3]);
                }
            }
        }
        // no trailing barrier: next prep writes the other A buffer; the next
        // iteration's barrier orders everything that matters.
    }
}

// ---------------------------------------------------------------------------
// Inputs: x[E,256] f32, cs[E,64] f32, W[64,256,256] f32, edge_index (unused).
// Output: f32 [E,256].
// ---------------------------------------------------------------------------
extern "C" void kernel_launch(void* const* d_in, const int* in_sizes, int n_in,
                              void* d_out, int out_size) {
    const float* x  = (const float*)d_in[0];
    const float* cs = (const float*)d_in[1];
    const float* W  = (const float*)d_in[2];
    float* out = (float*)d_out;
    (void)in_sizes; (void)n_in; (void)out_size;

    int nsm = 148;
    cudaDeviceGetAttribute(&nsm, cudaDevAttrMultiProcessorCount, 0);

    cudaFuncSetAttribute(rgcn_hmma_kernel,
                         cudaFuncAttributeMaxDynamicSharedMemorySize, SM_TOT);

    wsum_part_kernel<<<1024, 256>>>(W);
    wsum_final_kernel<<<R_N, O_N>>>();
    rgcn_hmma_kernel<<<2 * nsm, 256, SM_TOT>>>(x, cs, out);
}

// round 13
// speedup vs baseline: 1.1513x; 1.1513x over previous
#include <cuda_runtime.h>
#include <cuda_fp16.h>
#include <cstdint>

#define E_N 100000
#define R_N 64
#define I_N 256
#define O_N 256
#define TILE_M 336
#define N_TILES ((E_N + TILE_M - 1) / TILE_M)   // 298 (<= 304 resident CTAs)

#define WSUM_BLOCKS 1024
#define XSUM_BLOCKS ((E_N + 7) / 8)              // 12500, 1 row per warp
#define FUSE_BLOCKS (WSUM_BLOCKS + XSUM_BLOCKS)

// main-kernel smem: single A buffer, hi+lo planes; init-only s_w overlays it
#define A_STRIDE 144                   // %128==16 -> conflict-free LDSM
#define A_BUF    (TILE_M * A_STRIDE)   // 48384
#define SM_TOT   (2 * A_BUF)           // 96768 -> 2 CTAs/SM

__device__ float g_wpart[16 * R_N * O_N];
__device__ float g_wsum[R_N * O_N];
__device__ float g_xsum[E_N];

// ---------------------------------------------------------------------------
// Kernel 1 (fused, proven R5 shape): blocks [0,1024) -> W partial sums;
// remaining blocks -> x row sums (1 row per warp).
// ---------------------------------------------------------------------------
__global__ __launch_bounds__(256, 8)
void fused_stream_kernel(const float* __restrict__ W,
                         const float* __restrict__ x) {
    const int bid = blockIdx.x;
    if (bid < WSUM_BLOCKS) {
        const int r = bid & 63;
        const int part = bid >> 6;
        const int o = threadIdx.x;
        const float* base = W + ((size_t)(r * I_N + part * 16)) * O_N + o;
        float s = 0.f;
#pragma unroll
        for (int i = 0; i < 16; ++i) s += base[(size_t)i * O_N];
        g_wpart[(part * R_N + r) * O_N + o] = s;
    } else {
        const int warp = threadIdx.x >> 5, lane = threadIdx.x & 31;
        const int row = (bid - WSUM_BLOCKS) * 8 + warp;
        if (row >= E_N) return;
        const float4* xp = (const float4*)x + (size_t)row * 64;
        float4 v0 = xp[lane], v1 = xp[lane + 32];
        float s = (v0.x + v0.y) + (v0.z + v0.w) + (v1.x + v1.y) + (v1.z + v1.w);
#pragma unroll
        for (int d = 16; d; d >>= 1) s += __shfl_xor_sync(0xffffffffu, s, d);
        if (lane == 0) g_xsum[row] = s;
    }
}

// ---------------------------------------------------------------------------
// Kernel 2: collapse W partials -> g_wsum.
// ---------------------------------------------------------------------------
__global__ void wsum_final_kernel() {
    const int r = blockIdx.x, o = threadIdx.x;
    float s = 0.f;
#pragma unroll
    for (int p = 0; p < 16; ++p) s += g_wpart[(p * R_N + r) * O_N + o];
    g_wsum[r * O_N + o] = s;
}

// ---------------------------------------------------------------------------
// helpers
// ---------------------------------------------------------------------------
static __device__ __forceinline__ void mma16816(float* acc, const uint32_t* a,
                                                uint32_t b0, uint32_t b1) {
    asm volatile(
        "mma.sync.aligned.m16n8k16.row.col.f32.f16.f16.f32 "
        "{%0,%1,%2,%3}, {%4,%5,%6,%7}, {%8,%9}, {%0,%1,%2,%3};"
        : "+f"(acc[0]), "+f"(acc[1]), "+f"(acc[2]), "+f"(acc[3])
        : "r"(a[0]), "r"(a[1]), "r"(a[2]), "r"(a[3]), "r"(b0), "r"(b1));
}
static __device__ __forceinline__ void ldsm4(uint32_t* r, uint32_t saddr) {
    asm volatile("ldmatrix.sync.aligned.m8n8.x4.shared.b16 {%0,%1,%2,%3}, [%4];"
                 : "=r"(r[0]), "=r"(r[1]), "=r"(r[2]), "=r"(r[3]) : "r"(saddr));
}
static __device__ __forceinline__ uint32_t pack2(__half a, __half b) {
    __half2 h; h.x = a; h.y = b;
    return *(uint32_t*)&h;
}
static __device__ __forceinline__ void split16(float v, __half& hi, __half& lo) {
    hi = __float2half_rn(v);
    lo = __float2half_rn(v - __half2float(hi));
}
// FMA-pipe reciprocal (no MUFU): magic seed + 2 Newton iterations
static __device__ __forceinline__ float frcp(float y) {
    float r = __uint_as_float(0x7EF311C3u - __float_as_uint(y));
    r = r * __fmaf_rn(-y, r, 2.0f);
    r = r * __fmaf_rn(-y, r, 2.0f);
    return r;
}

// ---------------------------------------------------------------------------
// Kernel 3: ONE tile per CTA (grid = N_TILES = 298, single wave, 2 CTAs/SM).
// init B frags -> prep A (direct cs LDG, 3 half-row passes) -> 1 barrier ->
// 21 x (LDSM + HMMA + STG) -> exit.  No loops over tiles, no double buffer.
// ---------------------------------------------------------------------------
__global__ __launch_bounds__(256, 2)
void rgcn_hmma_kernel(const float* __restrict__ cs,
                      float* __restrict__ out) {
    extern __shared__ __align__(16) char sm[];
    const uint32_t sbase = (uint32_t)__cvta_generic_to_shared(sm);
    const int t = threadIdx.x;
    const int warp = t >> 5, lane = t & 31;

    // ---- init: stage Wsum in smem (overlays A planes), extract B frags ----
    float* s_w = (float*)sm;
#pragma unroll 4
    for (int i = 0; i < 64; ++i) {
        int idx = i * 256 + t;
        s_w[idx] = g_wsum[idx];
    }
    __syncthreads();

    uint32_t bh[4][4][2], bl[4][4][2];
    {
        const int n = warp * 32 + (lane >> 2);
#pragma unroll
        for (int nt = 0; nt < 4; ++nt)
#pragma unroll
            for (int ks = 0; ks < 4; ++ks) {
                int kb = ks * 16 + 2 * (lane & 3);
                int nn = n + nt * 8;
                float w00 = s_w[kb * 256 + nn];
                float w01 = s_w[(kb + 1) * 256 + nn];
                float w10 = s_w[(kb + 8) * 256 + nn];
                float w11 = s_w[(kb + 9) * 256 + nn];
                __half h00, l00, h01, l01, h10, l10, h11, l11;
                split16(w00, h00, l00); split16(w01, h01, l01);
                split16(w10, h10, l10); split16(w11, h11, l11);
                bh[nt][ks][0] = pack2(h00, h01); bh[nt][ks][1] = pack2(h10, h11);
                bl[nt][ks][0] = pack2(l00, l01); bl[nt][ks][1] = pack2(l10, l11);
            }
    }
    __syncthreads();   // s_w dead; A planes writable

    const int ebase = blockIdx.x * TILE_M;
    const int el = t >> 1, kh = t & 1;   // half-row prep mapping
    const float4* __restrict__ cs4 = (const float4*)cs;

    // ================= PREP: 3 passes of 128 rows (last pass 80) ============
#pragma unroll
    for (int p = 0; p < 3; ++p) {
        const int row = p * 128 + el;
        if (row < TILE_M) {
            int e = ebase + row;
            if (e > E_N - 1) e = E_N - 1;
            float xs = g_xsum[e];
            const float4* cp = cs4 + (size_t)e * 16 + kh * 8;
            uint32_t hw[16], lw[16];
#pragma unroll
            for (int q = 0; q < 8; ++q) {
                float4 c = cp[q];
                float v0 = xs * frcp(c.x);
                float v1 = xs * frcp(c.y);
                float v2 = xs * frcp(c.z);
                float v3 = xs * frcp(c.w);
                __half h0, l0, h1, l1, h2, l2, h3, l3;
                split16(v0, h0, l0); split16(v1, h1, l1);
                split16(v2, h2, l2); split16(v3, h3, l3);
                hw[2 * q] = pack2(h0, h1); hw[2 * q + 1] = pack2(h2, h3);
                lw[2 * q] = pack2(l0, l1); lw[2 * q + 1] = pack2(l2, l3);
            }
            uint32_t off = row * A_STRIDE + kh * 64;
            uint4* dh = (uint4*)(sm + off);
            uint4* dl = (uint4*)(sm + off + A_BUF);
#pragma unroll
            for (int q = 0; q < 4; ++q) {
                dh[q] = make_uint4(hw[4 * q], hw[4 * q + 1], hw[4 * q + 2], hw[4 * q + 3]);
                dl[q] = make_uint4(lw[4 * q], lw[4 * q + 1], lw[4 * q + 2], lw[4 * q + 3]);
            }
        }
    }
    __syncthreads();   // A ready — the only barrier on the tile path

    // ================= MMA + STORE: 21 x 16-row slabs =======================
    {
        const uint32_t ah_base = sbase;
        const uint32_t al_base = sbase + A_BUF;
        const uint32_t lrow = (lane & 7) + ((lane >> 3) & 1) * 8;
        const uint32_t lcol = (lane >> 4) * 16;
        const int gr = lane >> 2;
        const int col = warp * 32 + (lane & 3) * 2;

#pragma unroll 1
        for (int m0 = 0; m0 < TILE_M; m0 += 16) {
            uint32_t fo = (m0 + lrow) * A_STRIDE + lcol;
            float acc[4][4];
#pragma unroll
            for (int nt = 0; nt < 4; ++nt)
                acc[nt][0] = acc[nt][1] = acc[nt][2] = acc[nt][3] = 0.f;
#pragma unroll
            for (int ks = 0; ks < 4; ++ks) {
                uint32_t ah[4], al[4];
                ldsm4(ah, ah_base + fo + ks * 32);
                ldsm4(al, al_base + fo + ks * 32);
#pragma unroll
                for (int nt = 0; nt < 4; ++nt) {
                    mma16816(acc[nt], ah, bh[nt][ks][0], bh[nt][ks][1]);
                    mma16816(acc[nt], ah, bl[nt][ks][0], bl[nt][ks][1]);
                    mma16816(acc[nt], al, bh[nt][ks][0], bh[nt][ks][1]);
                }
            }
            int e0 = ebase + m0 + gr, e1 = e0 + 8;
            if (e0 < E_N) {
                float* p = out + (size_t)e0 * O_N + col;
#pragma unroll
                for (int nt = 0; nt < 4; ++nt)
                    *(float2*)(p + nt * 8) = make_float2(acc[nt][0], acc[nt][1]);
            }
            if (e1 < E_N) {
                float* p = out + (size_t)e1 * O_N + col;
#pragma unroll
                for (int nt = 0; nt < 4; ++nt)
                    *(float2*)(p + nt * 8) = make_float2(acc[nt][2], acc[nt][3]);
            }
        }
    }
}

// ---------------------------------------------------------------------------
// Inputs: x[E,256] f32, cs[E,64] f32, W[64,256,256] f32, edge_index (unused).
// Output: f32 [E,256].
// ---------------------------------------------------------------------------
extern "C" void kernel_launch(void* const* d_in, const int* in_sizes, int n_in,
                              void* d_out, int out_size) {
    const float* x  = (const float*)d_in[0];
    const float* cs = (const float*)d_in[1];
    const float* W  = (const float*)d_in[2];
    float* out = (float*)d_out;
    (void)in_sizes; (void)n_in; (void)out_size;

    cudaFuncSetAttribute(rgcn_hmma_kernel,
                         cudaFuncAttributeMaxDynamicSharedMemorySize, SM_TOT);

    fused_stream_kernel<<<FUSE_BLOCKS, 256>>>(W, x);
    wsum_final_kernel<<<R_N, O_N>>>();
    rgcn_hmma_kernel<<<N_TILES, 256, SM_TOT>>>(cs, out);
}